// round 17
// baseline (speedup 1.0000x reference)
#include <cuda_runtime.h>
#include <math.h>

#define LRW 256
#define LRH 256
#define HRW 1024
#define HRH 1024
#define NC 3
#define RAD 4

#define LRN (NC * LRH * LRW)
#define SC (255.0f / 1023.0f)

typedef unsigned long long u64;

// Scratch (no cudaMalloc allowed) — device globals.
__device__ float g_A[LRN];
__device__ float g_B[LRN];

// ---------------------------------------------------------------------------
// Packed f32x2 helpers (sm_103a): one instruction operates on (A,B) lanes.
// ---------------------------------------------------------------------------
__device__ __forceinline__ float f2lo(u64 v) {
    return __uint_as_float((unsigned)(v & 0xffffffffu));
}
__device__ __forceinline__ float f2hi(u64 v) {
    return __uint_as_float((unsigned)(v >> 32));
}
__device__ __forceinline__ u64 addx2(u64 a, u64 b) {
    u64 r; asm("add.rn.f32x2 %0,%1,%2;" : "=l"(r) : "l"(a), "l"(b)); return r;
}
__device__ __forceinline__ u64 mulx2(u64 a, u64 b) {
    u64 r; asm("mul.rn.f32x2 %0,%1,%2;" : "=l"(r) : "l"(a), "l"(b)); return r;
}
__device__ __forceinline__ u64 fmax2(u64 a, u64 b, u64 c) {
    u64 r; asm("fma.rn.f32x2 %0,%1,%2,%3;" : "=l"(r) : "l"(a), "l"(b), "l"(c)); return r;
}
__device__ __forceinline__ u64 bcastx2(float x) {
    u64 r; asm("mov.b64 %0,{%1,%1};" : "=l"(r) : "f"(x)); return r;
}
#define NEG1X2 0xBF800000BF800000ull   // packed (-1.f, -1.f)

// load 12 packed (A,B) values = 24 floats = 6 LDS.128
__device__ __forceinline__ void load12x2(u64* v, const float* base) {
#pragma unroll
    for (int i = 0; i < 6; ++i) {
        ulonglong2 q = *reinterpret_cast<const ulonglong2*>(base + 4 * i);
        v[2 * i] = q.x; v[2 * i + 1] = q.y;
    }
}

// packed sliding 5-window sums, left-associated like the scalar version
__device__ __forceinline__ void hsum5x2(u64* h, const u64* v) {
    h[0] = addx2(addx2(addx2(addx2(v[0], v[1]), v[2]), v[3]), v[4]);
#pragma unroll
    for (int i = 1; i < 8; ++i)
        h[i] = addx2(fmax2(v[i - 1], NEG1X2, h[i - 1]), v[i + 4]);
}

// packed S-row load: h sums + center cols (v[4..7])
__device__ __forceinline__ void loadrowx2(const float* base, u64* h, u64* cc) {
    u64 v[12];
    load12x2(v, base);
    hsum5x2(h, v);
    cc[0] = v[4]; cc[1] = v[5]; cc[2] = v[6]; cc[3] = v[7];
}

// scalar helpers for lr_fused
__device__ __forceinline__ void load12(float* v, const float* base) {
    float4 q0 = *reinterpret_cast<const float4*>(base);
    float4 q1 = *reinterpret_cast<const float4*>(base + 4);
    float4 q2 = *reinterpret_cast<const float4*>(base + 8);
    v[0]=q0.x; v[1]=q0.y; v[2]=q0.z;  v[3]=q0.w;
    v[4]=q1.x; v[5]=q1.y; v[6]=q1.z;  v[7]=q1.w;
    v[8]=q2.x; v[9]=q2.y; v[10]=q2.z; v[11]=q2.w;
}

// ---------------------------------------------------------------------------
// Fused low-res kernel: tile 16x16 per block (grid 16x16x3), 256 threads.
// (round-14 version, unchanged)
// ---------------------------------------------------------------------------
#define LTS 16
#define LEX 24
#define LSP 28

__global__ void __launch_bounds__(256) lr_fused(const float* __restrict__ lrx,
                                                const float* __restrict__ lry,
                                                const float* __restrict__ boxw) {
    __shared__ __align__(16) float Xs[LEX * LSP];
    __shared__ __align__(16) float Ys[LEX * LSP];
    __shared__ __align__(16) float Vx[LTS * LSP];
    __shared__ __align__(16) float Vy[LTS * LSP];
    __shared__ __align__(16) float Vxy[LTS * LSP];
    __shared__ __align__(16) float Vxx[LTS * LSP];

    const int c = blockIdx.z;
    const int x0t = blockIdx.x * LTS;
    const int y0t = blockIdx.y * LTS;
    const int tid = threadIdx.x;
    const float* __restrict__ px = lrx + c * LRH * LRW;
    const float* __restrict__ py = lry + c * LRH * LRW;

    for (int j = tid; j < LEX * LEX; j += 256) {
        int ly = j / LEX, lx = j % LEX;
        int Y = y0t - RAD + ly; Y = Y < 0 ? 0 : (Y > LRH - 1 ? LRH - 1 : Y);
        int X = x0t - RAD + lx; X = X < 0 ? 0 : (X > LRW - 1 ? LRW - 1 : X);
        Xs[ly * LSP + lx] = px[Y * LRW + X];
        Ys[ly * LSP + lx] = py[Y * LRW + X];
    }
    __syncthreads();

    for (int j = tid; j < LTS * LEX; j += 256) {
        int ry = j / LEX, lx = j % LEX;
        float sx = 0.f, sy = 0.f, sxy = 0.f, sxx = 0.f;
#pragma unroll
        for (int k = 0; k < 9; ++k) {
            float vx = Xs[(ry + k) * LSP + lx];
            float vy = Ys[(ry + k) * LSP + lx];
            sx += vx; sy += vy; sxy += vx * vy; sxx += vx * vx;
        }
        Vx[ry * LSP + lx] = sx;  Vy[ry * LSP + lx] = sy;
        Vxy[ry * LSP + lx] = sxy; Vxx[ry * LSP + lx] = sxx;
    }
    __syncthreads();

    if (tid < 64) {
        const int ty = tid >> 2;            // 0..15
        const int x0 = (tid & 3) << 2;      // 0,4,8,12
        float vx[12], vy[12], vxy[12], vxx[12];
        load12(vx,  &Vx[ty * LSP + x0]);
        load12(vy,  &Vy[ty * LSP + x0]);
        load12(vxy, &Vxy[ty * LSP + x0]);
        load12(vxx, &Vxx[ty * LSP + x0]);

        float hx[4], hy[4], hxy[4], hxx[4];
        hx[0] = vx[0]+vx[1]+vx[2]+vx[3]+vx[4]+vx[5]+vx[6]+vx[7]+vx[8];
        hy[0] = vy[0]+vy[1]+vy[2]+vy[3]+vy[4]+vy[5]+vy[6]+vy[7]+vy[8];
        hxy[0]= vxy[0]+vxy[1]+vxy[2]+vxy[3]+vxy[4]+vxy[5]+vxy[6]+vxy[7]+vxy[8];
        hxx[0]= vxx[0]+vxx[1]+vxx[2]+vxx[3]+vxx[4]+vxx[5]+vxx[6]+vxx[7]+vxx[8];
#pragma unroll
        for (int i = 1; i < 4; ++i) {
            hx[i]  = hx[i-1]  - vx[i-1]  + vx[i+8];
            hy[i]  = hy[i-1]  - vy[i-1]  + vy[i+8];
            hxy[i] = hxy[i-1] - vxy[i-1] + vxy[i+8];
            hxx[i] = hxx[i-1] - vxx[i-1] + vxx[i+8];
        }

        const float w = boxw[c * 81];
        float A_[4], B_[4];
#pragma unroll
        for (int p = 0; p < 4; ++p) {
            float mx = hx[p] * w, my = hy[p] * w, mxy = hxy[p] * w, mxx = hxx[p] * w;
            float A = (mxy - mx * my) / (mxx - mx * mx + 2.0f);   // EPS = 2
            A_[p] = A; B_[p] = my - A * mx;
        }
        int o = c * LRH * LRW + (y0t + ty) * LRW + (x0t + x0);
        *reinterpret_cast<float4*>(&g_A[o]) = make_float4(A_[0], A_[1], A_[2], A_[3]);
        *reinterpret_cast<float4*>(&g_B[o]) = make_float4(B_[0], B_[1], B_[2], B_[3]);
    }
}

// ---------------------------------------------------------------------------
// HR fused: block = 128-col x 16-row tile (grid 8x64x3), 256 threads, (256,3).
// Round-17 change: all S/U/staged-AB storage is INTERLEAVED (A,B) per column
// and all field-parallel math (F2 lerps/ring sums, phase-3 hsum5) uses packed
// f32x2 instructions -> ~half the arithmetic instructions in the hot paths.
// Pairing + argmin structure unchanged.
// ---------------------------------------------------------------------------
#define XT 128
#define YS 16
#define SIP 276          // interleaved row stride in floats (136 col-pairs + pad)
#define SR 20
#define UR 16
#define EXR 24
#define UOFF2 (SR * SIP)
#define ABR 10
#define ABC 36
#define AB2P 74          // interleaved A/B stage stride (2*36 + pad)
#define PCOLS 136

// horizontal lerp of one interleaved AB row at column i0 (packed)
__device__ __forceinline__ u64 hl_lerp(const float* sABi, int k, int i0,
                                       u64 OFX2, u64 FX2) {
    u64 p0 = *reinterpret_cast<const u64*>(sABi + k * AB2P + 2 * i0);
    u64 p1 = *reinterpret_cast<const u64*>(sABi + k * AB2P + 2 * i0 + 2);
    return fmax2(p1, FX2, mulx2(p0, OFX2));
}

// one output row of 4 px from packed rows
__device__ __forceinline__ void emit_row_x2(
    float* outp, const float4 im4,
    const u64* hT, const u64* cT,   // top S sums + top center cols
    const u64* hB, const u64* cB,   // bot S sums + bot center cols
    const u64* hC)                  // center-row U sums
{
    const float i45 = 1.0f / 45.0f, i25 = 1.0f / 25.0f;
    const float imv[4] = {im4.x, im4.y, im4.z, im4.w};
    float res[4];
#pragma unroll
    for (int p = 0; p < 4; ++p) {
        const float im = imv[p];
        float Ptl = fmaf(f2lo(hT[p]),     im, f2hi(hT[p]));
        float Ptr = fmaf(f2lo(hT[p + 4]), im, f2hi(hT[p + 4]));
        float Pbl = fmaf(f2lo(hB[p]),     im, f2hi(hB[p]));
        float Pbr = fmaf(f2lo(hB[p + 4]), im, f2hi(hB[p + 4]));
        float Pcl = fmaf(f2lo(hC[p]),     im, f2hi(hC[p]));
        float Pcr = fmaf(f2lo(hC[p + 4]), im, f2hi(hC[p + 4]));
        float Ptc = fmaf(f2lo(cT[p]),     im, f2hi(cT[p]));
        float Pbc = fmaf(f2lo(cB[p]),     im, f2hi(cB[p]));

        float d0 = fmaf(Ptl + Pbl - Pcl, i45, -im);  // L
        float d1 = fmaf(Ptr + Pbr - Pcr, i45, -im);  // R
        float d2 = fmaf(Ptl + Ptr - Ptc, i45, -im);  // U
        float d3 = fmaf(Pbl + Pbr - Pbc, i45, -im);  // D
        float d4 = fmaf(Ptl, i25, -im);              // NW
        float d5 = fmaf(Ptr, i25, -im);              // NE
        float d6 = fmaf(Pbl, i25, -im);              // SW
        float d7 = fmaf(Pbr, i25, -im);              // SE

        float bestA = fminf(fminf(fminf(fabsf(d0), fabsf(d1)),
                                  fminf(fabsf(d2), fabsf(d3))),
                            fminf(fminf(fabsf(d4), fabsf(d5)),
                                  fminf(fabsf(d6), fabsf(d7))));
        float best = d7;
        if (fabsf(d6) == bestA) best = d6;
        if (fabsf(d5) == bestA) best = d5;
        if (fabsf(d4) == bestA) best = d4;
        if (fabsf(d3) == bestA) best = d3;
        if (fabsf(d2) == bestA) best = d2;
        if (fabsf(d1) == bestA) best = d1;
        if (fabsf(d0) == bestA) best = d0;

        float r = truncf(best + im);
        res[p] = fminf(fmaxf(r, 0.0f), 255.0f);
    }
    *reinterpret_cast<float4*>(outp) = make_float4(res[0], res[1], res[2], res[3]);
}

__global__ void __launch_bounds__(256, 3) hr_fused(const float* __restrict__ hrx,
                                                   float* __restrict__ out) {
    __shared__ __align__(16) float sm[(SR + UR) * SIP];    // 39.7 KB interleaved S+U
    __shared__ __align__(16) float sABi[ABR * AB2P];       // 2.96 KB interleaved A,B
    __shared__ int   s_ek[EXR];
    __shared__ float s_efy[EXR];
    __shared__ int   s_cix[PCOLS];
    __shared__ float s_cfx[PCOLS];

    const int c  = blockIdx.z;
    const int X0 = blockIdx.x * XT;
    const int Y0 = blockIdx.y * YS;
    const int tid = threadIdx.x;

    // block-uniform base LR row / col
    int Yb = Y0 - 4; Yb = Yb < 0 ? 0 : Yb;
    int jbase = (int)floorf((float)Yb * SC);
    if (jbase > LRH - 2) jbase = LRH - 2;
    int Xb = X0 - 4; Xb = Xb < 0 ? 0 : Xb;
    int ixbase = (int)floorf((float)Xb * SC);
    if (ixbase > LRW - 2) ixbase = LRW - 2;

    // ---- thread's pair mapping: rows r and r+4, 4-px column xl ----
    const int rw = tid >> 5;                       // 0..7
    const int xl = (tid & 31) << 2;                // 0..124
    const int r  = (rw & 3) + ((rw >> 2) << 3);    // 0..3, 8..11

    // ---- Prefetch hrx rows r and r+4 ----
    float4 im0 = *reinterpret_cast<const float4*>(
        &hrx[(c * HRH + Y0 + r) * HRW + X0 + xl]);
    float4 im1 = *reinterpret_cast<const float4*>(
        &hrx[(c * HRH + Y0 + r + 4) * HRW + X0 + xl]);

    // ---- Phase W: ext-row table + column table ----
    if (tid < EXR) {
        int Y = Y0 - 4 + tid; Y = Y < 0 ? 0 : (Y > HRH - 1 ? HRH - 1 : Y);
        float tt = (float)Y * SC;
        int iy = (int)floorf(tt); if (iy > LRH - 2) iy = LRH - 2;
        s_ek[tid]  = iy - jbase;
        s_efy[tid] = tt - (float)iy;
    } else if (tid >= 32 && tid < 32 + PCOLS) {
        int lx = tid - 32;
        int X = X0 - 4 + lx; X = X < 0 ? 0 : (X > HRW - 1 ? HRW - 1 : X);
        float tt = (float)X * SC;
        int ix = (int)floorf(tt); if (ix > LRW - 2) ix = LRW - 2;
        s_cix[lx] = ix - ixbase;           // 0..34; +1 <= 35 < ABC
        s_cfx[lx] = tt - (float)ix;
    }

    // ---- Phase F0: stage A,B interleaved (2 coalesced LDG + 1 STS.64) ----
    for (int it = tid; it < ABR * ABC; it += 256) {
        int k   = it / ABC;
        int col = it - k * ABC;
        int lr = jbase + k; if (lr > LRH - 1) lr = LRH - 1;
        int gx = ixbase + col; if (gx > LRW - 1) gx = LRW - 1;
        float a = g_A[(c * LRH + lr) * LRW + gx];
        float b = g_B[(c * LRH + lr) * LRW + gx];
        *reinterpret_cast<float2*>(&sABi[k * AB2P + 2 * col]) = make_float2(a, b);
    }
    __syncthreads();

    // ---- Phase F2: sliding vertical pass, packed (A,B), one col/thread ----
    if (tid < PCOLS) {
        const int i0 = s_cix[tid];
        const float fx = s_cfx[tid];
        const u64 FX2  = bcastx2(fx);
        const u64 OFX2 = bcastx2(1.0f - fx);
        float* Sout = &sm[2 * tid];
        float* Uout = &sm[UOFF2 + 2 * tid];

        u64 h0 = hl_lerp(sABi, 0, i0, OFX2, FX2);
        u64 h1 = hl_lerp(sABi, 1, i0, OFX2, FX2);
        int kcur = 0;
        u64 ring[5];
#pragma unroll
        for (int e = 0; e < EXR; ++e) {
            int ke = s_ek[e];
            if (ke != kcur) {                // advances by exactly 1
                h0 = h1;
                h1 = hl_lerp(sABi, ke + 1, i0, OFX2, FX2);
                kcur = ke;
            }
            float fy = s_efy[e];
            u64 FY2  = bcastx2(fy);
            u64 OFY2 = bcastx2(1.0f - fy);
            u64 u = fmax2(h1, FY2, mulx2(h0, OFY2));
            ring[e % 5] = u;
            if (e >= 4) {
                u64 s = addx2(addx2(addx2(addx2(ring[0], ring[1]), ring[2]),
                                    ring[3]), ring[4]);
                *reinterpret_cast<u64*>(Sout + (e - 4) * SIP) = s;
                if (e < 4 + UR)
                    *reinterpret_cast<u64*>(Uout + (e - 4) * SIP) = u;
            }
        }
    }
    __syncthreads();

    // ---- Phase 3: paired rows r, r+4 (packed loads + packed hsum5) ----
    u64 hT[8], cT[4], hM[8], cM[4];
    loadrowx2(&sm[r * SIP + 2 * xl],       hT, cT);
    loadrowx2(&sm[(r + 4) * SIP + 2 * xl], hM, cM);

    // row r: top=(hT,cT), bot=(hM,cM)
    {
        u64 vv[12], hC[8];
        load12x2(vv, &sm[UOFF2 + r * SIP + 2 * xl]);
        hsum5x2(hC, vv);
        emit_row_x2(&out[(c * HRH + Y0 + r) * HRW + X0 + xl], im0,
                    hT, cT, hM, cM, hC);
    }

    // row r+4: top=(hM,cM), bot=S[r+8]
    {
        u64 hB8[8], cB4[4];
        loadrowx2(&sm[(r + 8) * SIP + 2 * xl], hB8, cB4);
        u64 vv[12], hC[8];
        load12x2(vv, &sm[UOFF2 + (r + 4) * SIP + 2 * xl]);
        hsum5x2(hC, vv);
        emit_row_x2(&out[(c * HRH + Y0 + r + 4) * HRW + X0 + xl], im1,
                    hM, cM, hB8, cB4, hC);
    }
}

// ---------------------------------------------------------------------------
extern "C" void kernel_launch(void* const* d_in, const int* in_sizes, int n_in,
                              void* d_out, int out_size) {
    const float* lrx  = (const float*)d_in[0];
    const float* lry  = (const float*)d_in[1];
    const float* hrx  = (const float*)d_in[2];
    const float* boxw = (const float*)d_in[3];
    float* out = (float*)d_out;

    dim3 lgrid(LRW / LTS, LRH / LTS, NC);
    lr_fused<<<lgrid, 256>>>(lrx, lry, boxw);

    dim3 grid(HRW / XT, HRH / YS, NC);
    hr_fused<<<grid, 256>>>(hrx, out);
}